// round 8
// baseline (speedup 1.0000x reference)
#include <cuda_runtime.h>

#define NN   28      // nodes
#define NA   32      // padded A row stride
#define RPB  64      // rows per block
#define TPB  128     // threads per block (2 threads per row)

// Transposed, padded adjacency: At32[s*32 + d] = A[d][s], zeros for d>=28.
__device__ float g_At32[NN * NA];
__device__ float g_meta[4];  // cp, cn, b2, general_flag

// ---------------------------------------------------------------------------
// Setup kernel (1 block): dtype-probe edge_index (int32 vs int64 words),
// build GCN-normalized adjacency, collapse the 64-wide MLP to (cp, cn).
// ---------------------------------------------------------------------------
__global__ void gcn_setup_kernel(const int* __restrict__ ei32, int n_elems,
                                 const float* __restrict__ W1,
                                 const float* __restrict__ b1,
                                 const float* __restrict__ W2,
                                 const float* __restrict__ b2, int H)
{
    __shared__ float deg[NN];
    __shared__ float dinv[NN];
    __shared__ float A[NN * NN];
    __shared__ int s_is32;
    int t = threadIdx.x;

    if (t == 0) s_is32 = 0;
    if (t < NN) deg[t] = 1.0f;                       // self-loop contributes 1
    for (int i = t; i < NN * NN; i += blockDim.x) A[i] = 0.0f;
    __syncthreads();

    // int64 LE with values <28 has all-zero odd int32 words; int32 doesn't.
    int found = 0;
    for (int i = 2 * t + 1; i < n_elems; i += 2 * blockDim.x)
        if (ei32[i] != 0) found = 1;
    if (found) atomicOr(&s_is32, 1);
    __syncthreads();

    const int is32 = s_is32;
    const int E = n_elems / 2;
    const int stride  = is32 ? 1 : 2;
    const int dstbase = is32 ? E : 2 * E;

    for (int e = t; e < E; e += blockDim.x) {
        int d = ei32[dstbase + stride * e];
        if (d >= 0 && d < NN) atomicAdd(&deg[d], 1.0f);
    }
    __syncthreads();

    if (t < NN) dinv[t] = deg[t] > 0.0f ? rsqrtf(deg[t]) : 0.0f;
    __syncthreads();

    for (int e = t; e < E; e += blockDim.x) {
        int s = ei32[stride * e];
        int d = ei32[dstbase + stride * e];
        if (s >= 0 && s < NN && d >= 0 && d < NN)
            atomicAdd(&A[d * NN + s], dinv[s] * dinv[d]);
    }
    if (t < NN) atomicAdd(&A[t * NN + t], dinv[t] * dinv[t]);
    __syncthreads();

    // transposed + padded store
    for (int i = t; i < NN * NA; i += blockDim.x) {
        int s = i / NA, d = i - s * NA;
        g_At32[i] = (d < NN) ? A[d * NN + s] : 0.0f;
    }

    if (t == 0) {
        float cp = 0.0f, cn = 0.0f;
        int general = 0;
        for (int o = 0; o < H; o++) {
            float w1 = W1[o], w2 = W2[o];
            if (w1 > 0.0f) cp += w1 * w2;
            else           cn += w1 * w2;
            if (b1[o] != 0.0f) general = 1;
        }
        g_meta[0] = cp;
        g_meta[1] = cn;
        g_meta[2] = b2[0];
        g_meta[3] = (float)general;
    }
}

// pick component of a float4 with a compile-time constant index
__device__ __forceinline__ float f4c(const float4& v, int c) {
    return (c == 0) ? v.x : (c == 1) ? v.y : (c == 2) ? v.z : v.w;
}

// Cold fallback (b1 != 0): per-component scalar accumulation.
__device__ __noinline__ void mlp_general16(float* y, int dbase,
                                           const float* __restrict__ W1,
                                           const float* __restrict__ b1,
                                           const float* __restrict__ W2, int H)
{
    #pragma unroll
    for (int j = 0; j < 16; j++) {
        if (dbase + j >= NN) break;
        float v = y[j], acc = 0.0f;
        for (int o = 0; o < H; o++)
            acc = fmaf(W2[o], fmaxf(fmaf(W1[o], v, b1[o]), 0.0f), acc);
        y[j] = acc;
    }
}

// ---------------------------------------------------------------------------
// Main kernel: 2 threads per row; thread q owns output components [16q,16q+16).
// x fully register-resident (whole row loaded by both threads, coalesced);
// z exchanged via shfl_xor(1) -> matvec2 needs no shared reads for z.
// Only shared use: the 28x32 adjacency (broadcast LDS). One barrier total.
// ---------------------------------------------------------------------------
__global__ void __launch_bounds__(TPB) gcn_main_kernel(
    const float* __restrict__ x, float* __restrict__ out,
    const float* __restrict__ W1, const float* __restrict__ b1,
    const float* __restrict__ W2, int H, int B)
{
    __shared__ float As[NN * NA];        // 3.5 KB
    const int t = threadIdx.x;
    const int q = t & 1;                 // half index: 0 -> cols 0..15, 1 -> 16..31
    const int r = t >> 1;                // local row 0..63

    for (int i = t; i < NN * NA; i += TPB) As[i] = g_At32[i];

    const float cp  = g_meta[0];
    const float cn  = g_meta[1];
    const float b2v = g_meta[2];
    const bool general = (g_meta[3] != 0.0f);
    __syncthreads();

    const long long row = (long long)blockIdx.x * RPB + r;
    if (row >= B) return;

    // ---- whole row into registers (7 LDG.128; lane pairs share lines) ----
    const float4* xp = (const float4*)(x + row * NN);
    float4 x4[7];
    #pragma unroll
    for (int k = 0; k < 7; k++) x4[k] = xp[k];

    const float* ap = As + q * 16;       // this thread's 16-wide A slice

    // ---- matvec 1: y[16] = A-slice . x ----
    float y[16];
    #pragma unroll
    for (int j = 0; j < 16; j++) y[j] = 0.0f;
    #pragma unroll
    for (int s = 0; s < NN; s++) {
        float xv = f4c(x4[s >> 2], s & 3);
        const float4 a0 = *(const float4*)(ap + s * NA);
        const float4 a1 = *(const float4*)(ap + s * NA + 4);
        const float4 a2 = *(const float4*)(ap + s * NA + 8);
        const float4 a3 = *(const float4*)(ap + s * NA + 12);
        y[ 0] = fmaf(a0.x, xv, y[ 0]);  y[ 1] = fmaf(a0.y, xv, y[ 1]);
        y[ 2] = fmaf(a0.z, xv, y[ 2]);  y[ 3] = fmaf(a0.w, xv, y[ 3]);
        y[ 4] = fmaf(a1.x, xv, y[ 4]);  y[ 5] = fmaf(a1.y, xv, y[ 5]);
        y[ 6] = fmaf(a1.z, xv, y[ 6]);  y[ 7] = fmaf(a1.w, xv, y[ 7]);
        y[ 8] = fmaf(a2.x, xv, y[ 8]);  y[ 9] = fmaf(a2.y, xv, y[ 9]);
        y[10] = fmaf(a2.z, xv, y[10]);  y[11] = fmaf(a2.w, xv, y[11]);
        y[12] = fmaf(a3.x, xv, y[12]);  y[13] = fmaf(a3.y, xv, y[13]);
        y[14] = fmaf(a3.z, xv, y[14]);  y[15] = fmaf(a3.w, xv, y[15]);
    }

    // ---- z = f(y)  (padded components stay 0: A cols >=28 are 0) ----
    if (!general) {
        #pragma unroll
        for (int j = 0; j < 16; j++)
            y[j] = cp * fmaxf(y[j], 0.0f) + cn * fminf(y[j], 0.0f);
    } else {
        mlp_general16(y, q * 16, W1, b1, W2, H);
    }

    // ---- assemble full z[28] in registers via partner-lane exchange ----
    float p[16];
    #pragma unroll
    for (int j = 0; j < 16; j++)
        p[j] = __shfl_xor_sync(0xFFFFFFFFu, y[j], 1);

    float z[NN];
    #pragma unroll
    for (int j = 0; j < 16; j++)       z[j]      = (q == 0) ? y[j] : p[j];
    #pragma unroll
    for (int j = 0; j < NN - 16; j++)  z[16 + j] = (q == 0) ? p[j] : y[j];

    // ---- matvec 2: o[16] = A-slice . z + b2 ----
    float o[16];
    #pragma unroll
    for (int j = 0; j < 16; j++) o[j] = b2v;
    #pragma unroll
    for (int s = 0; s < NN; s++) {
        float zv = z[s];
        const float4 a0 = *(const float4*)(ap + s * NA);
        const float4 a1 = *(const float4*)(ap + s * NA + 4);
        const float4 a2 = *(const float4*)(ap + s * NA + 8);
        const float4 a3 = *(const float4*)(ap + s * NA + 12);
        o[ 0] = fmaf(a0.x, zv, o[ 0]);  o[ 1] = fmaf(a0.y, zv, o[ 1]);
        o[ 2] = fmaf(a0.z, zv, o[ 2]);  o[ 3] = fmaf(a0.w, zv, o[ 3]);
        o[ 4] = fmaf(a1.x, zv, o[ 4]);  o[ 5] = fmaf(a1.y, zv, o[ 5]);
        o[ 6] = fmaf(a1.z, zv, o[ 6]);  o[ 7] = fmaf(a1.w, zv, o[ 7]);
        o[ 8] = fmaf(a2.x, zv, o[ 8]);  o[ 9] = fmaf(a2.y, zv, o[ 9]);
        o[10] = fmaf(a2.z, zv, o[10]);  o[11] = fmaf(a2.w, zv, o[11]);
        o[12] = fmaf(a3.x, zv, o[12]);  o[13] = fmaf(a3.y, zv, o[13]);
        o[14] = fmaf(a3.z, zv, o[14]);  o[15] = fmaf(a3.w, zv, o[15]);
    }

    // ---- store own 16 (or 12) components, coalesced float4 ----
    float* op = out + row * NN + q * 16;
    #pragma unroll
    for (int k = 0; k < 4; k++) {
        if (q * 16 + k * 4 < NN)
            *(float4*)(op + k * 4) =
                make_float4(o[4*k+0], o[4*k+1], o[4*k+2], o[4*k+3]);
    }
}

extern "C" void kernel_launch(void* const* d_in, const int* in_sizes, int n_in,
                              void* d_out, int out_size)
{
    const float* x  = (const float*)d_in[0];
    const int*   ei = (const int*)d_in[1];     // int32 view; dtype probed on-device
    const float* W1 = (const float*)d_in[2];
    const float* b1 = (const float*)d_in[3];
    const float* W2 = (const float*)d_in[4];
    const float* b2 = (const float*)d_in[5];
    float* out = (float*)d_out;

    int B = in_sizes[0] / NN;
    int n_edge_elems = in_sizes[1];
    int H = in_sizes[3];

    gcn_setup_kernel<<<1, 256>>>(ei, n_edge_elems, W1, b1, W2, b2, H);
    int grid = (B + RPB - 1) / RPB;
    gcn_main_kernel<<<grid, TPB>>>(x, out, W1, b1, W2, H, B);
}

// round 9
// speedup vs baseline: 2.8976x; 2.8976x over previous
#include <cuda_runtime.h>

#define NN   28      // nodes
#define NA   32      // padded A row stride
#define RPB  128     // rows per block
#define TPB  128     // threads: 32 groups x 4 threads; each group does 4 rows
#define SR   132     // transposed stage row stride (floats, multiple of 4)

// Transposed, padded adjacency: At32[s*32 + d] = A[d][s], zeros for d>=28.
__device__ float g_At32[NN * NA];
__device__ float g_meta[4];  // cp, cn, b2, general_flag

// ---------------------------------------------------------------------------
// Setup kernel (1 block): dtype-probe edge_index (int32 vs int64 words),
// build GCN-normalized adjacency, collapse the 64-wide MLP to (cp, cn).
// ---------------------------------------------------------------------------
__global__ void gcn_setup_kernel(const int* __restrict__ ei32, int n_elems,
                                 const float* __restrict__ W1,
                                 const float* __restrict__ b1,
                                 const float* __restrict__ W2,
                                 const float* __restrict__ b2, int H)
{
    __shared__ float deg[NN];
    __shared__ float dinv[NN];
    __shared__ float A[NN * NN];
    __shared__ int s_is32;
    int t = threadIdx.x;

    if (t == 0) s_is32 = 0;
    if (t < NN) deg[t] = 1.0f;                       // self-loop contributes 1
    for (int i = t; i < NN * NN; i += blockDim.x) A[i] = 0.0f;
    __syncthreads();

    // int64 LE with values <28 has all-zero odd int32 words; int32 doesn't.
    int found = 0;
    for (int i = 2 * t + 1; i < n_elems; i += 2 * blockDim.x)
        if (ei32[i] != 0) found = 1;
    if (found) atomicOr(&s_is32, 1);
    __syncthreads();

    const int is32 = s_is32;
    const int E = n_elems / 2;
    const int stride  = is32 ? 1 : 2;
    const int dstbase = is32 ? E : 2 * E;

    for (int e = t; e < E; e += blockDim.x) {
        int d = ei32[dstbase + stride * e];
        if (d >= 0 && d < NN) atomicAdd(&deg[d], 1.0f);
    }
    __syncthreads();

    if (t < NN) dinv[t] = deg[t] > 0.0f ? rsqrtf(deg[t]) : 0.0f;
    __syncthreads();

    for (int e = t; e < E; e += blockDim.x) {
        int s = ei32[stride * e];
        int d = ei32[dstbase + stride * e];
        if (s >= 0 && s < NN && d >= 0 && d < NN)
            atomicAdd(&A[d * NN + s], dinv[s] * dinv[d]);
    }
    if (t < NN) atomicAdd(&A[t * NN + t], dinv[t] * dinv[t]);
    __syncthreads();

    // transposed + padded store
    for (int i = t; i < NN * NA; i += blockDim.x) {
        int s = i / NA, d = i - s * NA;
        g_At32[i] = (d < NN) ? A[d * NN + s] : 0.0f;
    }

    if (t == 0) {
        float cp = 0.0f, cn = 0.0f;
        int general = 0;
        for (int o = 0; o < H; o++) {
            float w1 = W1[o], w2 = W2[o];
            if (w1 > 0.0f) cp += w1 * w2;
            else           cn += w1 * w2;
            if (b1[o] != 0.0f) general = 1;
        }
        g_meta[0] = cp;
        g_meta[1] = cn;
        g_meta[2] = b2[0];
        g_meta[3] = (float)general;
    }
}

// pick component of a float4 with a compile-time constant index
__device__ __forceinline__ float f4c(const float4& v, int c) {
    return (c == 0) ? v.x : (c == 1) ? v.y : (c == 2) ? v.z : v.w;
}

// ---------------------------------------------------------------------------
// Main kernel: thread (q, g) computes output comps [8q, 8q+8) of rows 4g..4g+3.
// x and z staged TRANSPOSED in shared: one LDS.128 per s yields 4 rows' values;
// the A slice is loaded once per s and reused across 4 rows (4x fewer A-LDS
// than R7). 32 accumulators -> no spills. 1792 FMAs/thread -> deep ILP.
// ---------------------------------------------------------------------------
__global__ void __launch_bounds__(TPB) gcn_main_kernel(
    const float* __restrict__ x, float* __restrict__ out,
    const float* __restrict__ W1, const float* __restrict__ b1,
    const float* __restrict__ W2, int H, int B)
{
    __shared__ float As[NN * NA];     // 3.5 KB
    __shared__ float xs[NN * SR];     // 14.4 KB: transposed x, then z
    const int t = threadIdx.x;
    const int q = t & 3;              // comp-block index
    const int g = t >> 2;             // row-group 0..31
    const int r0 = g * 4;

    for (int i = t; i < NN * NA; i += TPB) As[i] = g_At32[i];

    const float cp  = g_meta[0];
    const float cn  = g_meta[1];
    const float b2v = g_meta[2];
    const bool general = (g_meta[3] != 0.0f);

    const long long rowbase = (long long)blockIdx.x * RPB;
    int nrows = (int)(B - rowbase); if (nrows > RPB) nrows = RPB;

    // ---- stage x transposed: xs[c*SR + r] = x[row r, comp c] ----
    const float* gx = x + rowbase * NN;
    for (int i = t; i < nrows * NN; i += TPB) {
        int r = i / NN, c = i - r * NN;
        xs[c * SR + r] = gx[i];
    }
    __syncthreads();

    const float* ap = As + q * 8;     // this thread's 8-wide A slice

    // ---- matvec 1: acc[row][j] = sum_s A[s][8q+j] * x[row][s] ----
    float acc[4][8];
    #pragma unroll
    for (int rw = 0; rw < 4; rw++)
        #pragma unroll
        for (int j = 0; j < 8; j++) acc[rw][j] = 0.0f;

    #pragma unroll
    for (int s = 0; s < NN; s++) {
        const float4 xv = *(const float4*)(xs + s * SR + r0);   // 4 rows at s
        const float4 a0 = *(const float4*)(ap + s * NA);
        const float4 a1 = *(const float4*)(ap + s * NA + 4);
        float av[8] = {a0.x, a0.y, a0.z, a0.w, a1.x, a1.y, a1.z, a1.w};
        #pragma unroll
        for (int rw = 0; rw < 4; rw++) {
            const float xr = f4c(xv, rw);
            #pragma unroll
            for (int j = 0; j < 8; j++)
                acc[rw][j] = fmaf(av[j], xr, acc[rw][j]);
        }
    }

    // ---- z = f(y) in registers ----
    if (!general) {
        #pragma unroll
        for (int rw = 0; rw < 4; rw++)
            #pragma unroll
            for (int j = 0; j < 8; j++)
                acc[rw][j] = cp * fmaxf(acc[rw][j], 0.0f)
                           + cn * fminf(acc[rw][j], 0.0f);
    } else {
        // cold path, inline, dynamic H loop (reg demand below hot path's)
        #pragma unroll
        for (int rw = 0; rw < 4; rw++)
            #pragma unroll
            for (int j = 0; j < 8; j++) {
                float v = acc[rw][j], a = 0.0f;
                for (int o = 0; o < H; o++)
                    a = fmaf(W2[o], fmaxf(fmaf(W1[o], v, b1[o]), 0.0f), a);
                acc[rw][j] = a;
            }
    }

    __syncthreads();   // all matvec-1 reads of xs complete before z overwrite

    // ---- publish z transposed: xs[d*SR + r0..r0+3] ----
    #pragma unroll
    for (int j = 0; j < 8; j++) {
        int d = q * 8 + j;
        if (d < NN)
            *(float4*)(xs + d * SR + r0) =
                make_float4(acc[0][j], acc[1][j], acc[2][j], acc[3][j]);
    }
    __syncthreads();

    // ---- matvec 2: acc[row][j] = b2 + sum_s A[s][8q+j] * z[row][s] ----
    #pragma unroll
    for (int rw = 0; rw < 4; rw++)
        #pragma unroll
        for (int j = 0; j < 8; j++) acc[rw][j] = b2v;

    #pragma unroll
    for (int s = 0; s < NN; s++) {
        const float4 zv = *(const float4*)(xs + s * SR + r0);
        const float4 a0 = *(const float4*)(ap + s * NA);
        const float4 a1 = *(const float4*)(ap + s * NA + 4);
        float av[8] = {a0.x, a0.y, a0.z, a0.w, a1.x, a1.y, a1.z, a1.w};
        #pragma unroll
        for (int rw = 0; rw < 4; rw++) {
            const float zr = f4c(zv, rw);
            #pragma unroll
            for (int j = 0; j < 8; j++)
                acc[rw][j] = fmaf(av[j], zr, acc[rw][j]);
        }
    }

    // ---- direct stores: per row, comps [8q, 8q+8) as 1-2 STG.128 ----
    #pragma unroll
    for (int rw = 0; rw < 4; rw++) {
        int lr = r0 + rw;
        if (lr < nrows) {
            float* op = out + (rowbase + lr) * NN + q * 8;
            *(float4*)op = make_float4(acc[rw][0], acc[rw][1],
                                       acc[rw][2], acc[rw][3]);
            if (q < 3)
                *(float4*)(op + 4) = make_float4(acc[rw][4], acc[rw][5],
                                                 acc[rw][6], acc[rw][7]);
        }
    }
}

extern "C" void kernel_launch(void* const* d_in, const int* in_sizes, int n_in,
                              void* d_out, int out_size)
{
    const float* x  = (const float*)d_in[0];
    const int*   ei = (const int*)d_in[1];     // int32 view; dtype probed on-device
    const float* W1 = (const float*)d_in[2];
    const float* b1 = (const float*)d_in[3];
    const float* W2 = (const float*)d_in[4];
    const float* b2 = (const float*)d_in[5];
    float* out = (float*)d_out;

    int B = in_sizes[0] / NN;
    int n_edge_elems = in_sizes[1];
    int H = in_sizes[3];

    gcn_setup_kernel<<<1, 256>>>(ei, n_edge_elems, W1, b1, W2, b2, H);
    int grid = (B + RPB - 1) / RPB;
    gcn_main_kernel<<<grid, TPB>>>(x, out, W1, b1, W2, H, B);
}

// round 10
// speedup vs baseline: 3.4433x; 1.1883x over previous
#include <cuda_runtime.h>

#define NN   28      // nodes
#define NA   32      // padded A row stride
#define RPB  64      // rows per block
#define TPB  128     // threads: 16 groups x 8 threads; each thread: 4 rows x 4 comps
#define SR   68      // transposed x/z stage row stride (multiple of 4)

// pick component of a float4 with a compile-time constant index
__device__ __forceinline__ float f4c(const float4& v, int c) {
    return (c == 0) ? v.x : (c == 1) ? v.y : (c == 2) ? v.z : v.w;
}

// ---------------------------------------------------------------------------
// Single fused kernel. Each block:
//   1. stages its 64 x-rows transposed into shared,
//   2. redundantly builds the GCN-normalized adjacency (transposed+padded)
//      from edge_index in shared (dtype-probed int32 vs int64 words),
//   3. collapses the 64-wide MLP to (cp, cn) when b1 == 0,
//   4. computes out = A . f(A . x) + b2 with 16 accumulators/thread.
// Thread (q = t&7, g = t>>3) owns comps [4q,4q+4) of rows [4g,4g+4).
// ---------------------------------------------------------------------------
__global__ void __launch_bounds__(TPB) gcn_fused_kernel(
    const float* __restrict__ x, float* __restrict__ out,
    const int* __restrict__ ei32, int n_elems,
    const float* __restrict__ W1, const float* __restrict__ b1,
    const float* __restrict__ W2, const float* __restrict__ b2,
    int H, int B)
{
    __shared__ float As[NN * NA];     // transposed adjacency: As[s*NA+d]=A[d][s]
    __shared__ float xs[NN * SR];     // transposed x, then z
    __shared__ float deg[NN];
    __shared__ float dinv[NN];
    __shared__ float wred[128];       // cp/cn partial sums
    __shared__ float s_cp, s_cn;

    const int t = threadIdx.x;
    const int q = t & 7;              // comp-block: comps [4q, 4q+4)
    const int g = t >> 3;             // row-group 0..15
    const int r0 = g * 4;

    // ---- init shared ----
    if (t < NN) deg[t] = 1.0f;        // self-loop contributes 1
    #pragma unroll
    for (int i = t; i < NN * NA; i += TPB) As[i] = 0.0f;

    // ---- stage this block's x rows, transposed: xs[c*SR + r] ----
    const long long rowbase = (long long)blockIdx.x * RPB;
    int nrows = (int)(B - rowbase); if (nrows > RPB) nrows = RPB;
    const float* gx = x + rowbase * NN;
    for (int i = t; i < nrows * NN; i += TPB) {
        int r = i / NN, c = i - r * NN;
        xs[c * SR + r] = gx[i];
    }

    // ---- dtype probe: int64 LE with ids <28 has all-zero odd int32 words ----
    int found = 0;
    for (int i = 2 * t + 1; i < n_elems; i += 2 * TPB)
        if (ei32[i] != 0) found = 1;
    const int is32 = __syncthreads_or(found);   // barrier also fences init+stage

    const int E = n_elems / 2;
    const int stride  = is32 ? 1 : 2;
    const int dstbase = is32 ? E : 2 * E;

    // ---- degrees ----
    for (int e = t; e < E; e += TPB) {
        int d = ei32[dstbase + stride * e];
        if (d >= 0 && d < NN) atomicAdd(&deg[d], 1.0f);
    }
    __syncthreads();
    if (t < NN) dinv[t] = deg[t] > 0.0f ? rsqrtf(deg[t]) : 0.0f;
    __syncthreads();

    // ---- adjacency, built directly transposed: As[s*NA + d] += w ----
    for (int e = t; e < E; e += TPB) {
        int s = ei32[stride * e];
        int d = ei32[dstbase + stride * e];
        if (s >= 0 && s < NN && d >= 0 && d < NN)
            atomicAdd(&As[s * NA + d], dinv[s] * dinv[d]);
    }
    if (t < NN) atomicAdd(&As[t * NA + t], dinv[t] * dinv[t]);

    // ---- MLP collapse: cp = sum_{W1>0} W1*W2, cn = sum_{W1<0} W1*W2 ----
    int gflag = 0;
    if (t < 64) {
        float p = 0.0f, n = 0.0f;
        for (int o = t; o < H; o += 64) {
            float w1 = W1[o], w2 = W2[o];
            if (w1 > 0.0f) p += w1 * w2;
            else           n += w1 * w2;
            if (b1[o] != 0.0f) gflag = 1;
        }
        wred[t] = p; wred[64 + t] = n;
    }
    const int general = __syncthreads_or(gflag);  // also fences As atomics
    if (t == 0) {
        float cpa = 0.0f, cna = 0.0f;
        #pragma unroll
        for (int i = 0; i < 64; i++) { cpa += wred[i]; cna += wred[64 + i]; }
        s_cp = cpa; s_cn = cna;
    }
    __syncthreads();
    const float cp = s_cp, cn = s_cn, b2v = b2[0];

    const float* ap = As + q * 4;     // this thread's 4-wide A slice

    // ---- matvec 1: acc[rw][j] = sum_s A[s][4q+j] * x[r0+rw][s] ----
    float acc[4][4];
    #pragma unroll
    for (int rw = 0; rw < 4; rw++)
        #pragma unroll
        for (int j = 0; j < 4; j++) acc[rw][j] = 0.0f;

    #pragma unroll
    for (int s = 0; s < NN; s++) {
        const float4 xv = *(const float4*)(xs + s * SR + r0);  // 4 rows at s
        const float4 a  = *(const float4*)(ap + s * NA);       // 4 comps at s
        #pragma unroll
        for (int rw = 0; rw < 4; rw++) {
            const float xr = f4c(xv, rw);
            acc[rw][0] = fmaf(a.x, xr, acc[rw][0]);
            acc[rw][1] = fmaf(a.y, xr, acc[rw][1]);
            acc[rw][2] = fmaf(a.z, xr, acc[rw][2]);
            acc[rw][3] = fmaf(a.w, xr, acc[rw][3]);
        }
    }

    // ---- z = f(y) ----
    if (!general) {
        #pragma unroll
        for (int rw = 0; rw < 4; rw++)
            #pragma unroll
            for (int j = 0; j < 4; j++)
                acc[rw][j] = cp * fmaxf(acc[rw][j], 0.0f)
                           + cn * fminf(acc[rw][j], 0.0f);
    } else {
        // cold fallback (b1 != 0): exact per-element MLP
        #pragma unroll
        for (int rw = 0; rw < 4; rw++)
            #pragma unroll
            for (int j = 0; j < 4; j++) {
                float v = acc[rw][j], a2 = 0.0f;
                for (int o = 0; o < H; o++)
                    a2 = fmaf(W2[o], fmaxf(fmaf(W1[o], v, b1[o]), 0.0f), a2);
                acc[rw][j] = a2;
            }
    }

    __syncthreads();   // matvec-1 reads of xs complete before z overwrite

    // ---- publish z transposed ----
    #pragma unroll
    for (int j = 0; j < 4; j++) {
        int d = q * 4 + j;
        if (d < NN)
            *(float4*)(xs + d * SR + r0) =
                make_float4(acc[0][j], acc[1][j], acc[2][j], acc[3][j]);
    }
    __syncthreads();

    // ---- matvec 2: acc[rw][j] = b2 + sum_s A[s][4q+j] * z[r0+rw][s] ----
    #pragma unroll
    for (int rw = 0; rw < 4; rw++)
        #pragma unroll
        for (int j = 0; j < 4; j++) acc[rw][j] = b2v;

    #pragma unroll
    for (int s = 0; s < NN; s++) {
        const float4 zv = *(const float4*)(xs + s * SR + r0);
        const float4 a  = *(const float4*)(ap + s * NA);
        #pragma unroll
        for (int rw = 0; rw < 4; rw++) {
            const float zr = f4c(zv, rw);
            acc[rw][0] = fmaf(a.x, zr, acc[rw][0]);
            acc[rw][1] = fmaf(a.y, zr, acc[rw][1]);
            acc[rw][2] = fmaf(a.z, zr, acc[rw][2]);
            acc[rw][3] = fmaf(a.w, zr, acc[rw][3]);
        }
    }

    // ---- direct coalesced stores: comps [4q, 4q+4) per owned row ----
    if (q * 4 < NN) {
        #pragma unroll
        for (int rw = 0; rw < 4; rw++) {
            int lr = r0 + rw;
            if (lr < nrows) {
                float* op = out + (rowbase + lr) * NN + q * 4;
                *(float4*)op = make_float4(acc[rw][0], acc[rw][1],
                                           acc[rw][2], acc[rw][3]);
            }
        }
    }
}

extern "C" void kernel_launch(void* const* d_in, const int* in_sizes, int n_in,
                              void* d_out, int out_size)
{
    const float* x  = (const float*)d_in[0];
    const int*   ei = (const int*)d_in[1];     // int32 view; dtype probed on-device
    const float* W1 = (const float*)d_in[2];
    const float* b1 = (const float*)d_in[3];
    const float* W2 = (const float*)d_in[4];
    const float* b2 = (const float*)d_in[5];
    float* out = (float*)d_out;

    int B = in_sizes[0] / NN;
    int n_edge_elems = in_sizes[1];
    int H = in_sizes[3];

    int grid = (B + RPB - 1) / RPB;
    gcn_fused_kernel<<<grid, TPB>>>(x, out, ei, n_edge_elems,
                                    W1, b1, W2, b2, H, B);
}